// round 9
// baseline (speedup 1.0000x reference)
#include <cuda_runtime.h>
#include <stdint.h>
#include <math.h>

#define N_ROUTES 7
#define PC_DIM   512
#define MC_DIM   128
#define KCLS     25
#define BSZ      4096
#define COLS     (KCLS * MC_DIM)        // 3200
#define VOTE_PER_B (N_ROUTES * COLS)    // 22400
#define PP_STRIDE (N_ROUTES * PC_DIM)   // 3584
#define QSCALE   32500.0f

__device__ float g_vote[(size_t)BSZ * VOTE_PER_B];                    // 367 MB
__device__ signed char g_Pa0[(size_t)BSZ * PP_STRIDE];
__device__ signed char g_Pa1[(size_t)BSZ * PP_STRIDE];
__device__ signed char g_Wb0[(size_t)N_ROUTES * COLS * PC_DIM];       // [n][col][d]
__device__ signed char g_Wb1[(size_t)N_ROUTES * COLS * PC_DIM];
__device__ float g_sP[(size_t)BSZ * N_ROUTES];                        // rowmax/QSCALE
__device__ float g_sW[(size_t)N_ROUTES * COLS];                       // colmax/QSCALE

__device__ __forceinline__ uint32_t smem_to_u32(const void* p) {
    uint32_t a;
    asm("{ .reg .u64 t; cvta.to.shared.u64 t, %1; cvt.u32.u64 %0, t; }"
        : "=r"(a) : "l"(p));
    return a;
}
__device__ __forceinline__ uint32_t usw64(uint32_t o) {     // SW64 swizzle
    return o ^ ((o >> 3) & 0x30);
}
__device__ __forceinline__ float warp_max32(float v) {
#pragma unroll
    for (int o = 16; o; o >>= 1) v = fmaxf(v, __shfl_xor_sync(0xffffffffu, v, o));
    return v;
}

// ---------------------------------------------------------------------------
// Prep P: per-(b,n) row max, quantize to int16, split into int8 digits.
// 2 rows per 256-thread block; 128 threads per row (4 floats each).
// ---------------------------------------------------------------------------
__global__ __launch_bounds__(256) void prep_p_q(const float* __restrict__ P) {
    __shared__ float s_m[8];
    const int tid  = threadIdx.x;
    const int half = tid >> 7;            // 0,1 : which row
    const int l128 = tid & 127;
    const size_t row = (size_t)blockIdx.x * 2 + half;   // in [0, B*N)
    const float4 x = ((const float4*)(P + row * PC_DIM))[l128];

    float m = fmaxf(fmaxf(fabsf(x.x), fabsf(x.y)), fmaxf(fabsf(x.z), fabsf(x.w)));
    m = warp_max32(m);
    if ((tid & 31) == 0) s_m[tid >> 5] = m;
    __syncthreads();
    float rm = fmaxf(fmaxf(s_m[half * 4], s_m[half * 4 + 1]),
                     fmaxf(s_m[half * 4 + 2], s_m[half * 4 + 3]));
    rm = fmaxf(rm, 1e-30f);
    if (l128 == 0) g_sP[row] = rm * (1.f / QSCALE);

    const float qs = QSCALE / rm;
    int q[4] = { __float2int_rn(x.x * qs), __float2int_rn(x.y * qs),
                 __float2int_rn(x.z * qs), __float2int_rn(x.w * qs) };
    char4 d0, d1;
    int a0;
    a0 = (q[0] + 128) >> 8; d0.x = (signed char)a0; d1.x = (signed char)(q[0] - (a0 << 8));
    a0 = (q[1] + 128) >> 8; d0.y = (signed char)a0; d1.y = (signed char)(q[1] - (a0 << 8));
    a0 = (q[2] + 128) >> 8; d0.z = (signed char)a0; d1.z = (signed char)(q[2] - (a0 << 8));
    a0 = (q[3] + 128) >> 8; d0.w = (signed char)a0; d1.w = (signed char)(q[3] - (a0 << 8));
    ((char4*)(g_Pa0 + row * PC_DIM))[l128] = d0;
    ((char4*)(g_Pa1 + row * PC_DIM))[l128] = d1;
}

// ---------------------------------------------------------------------------
// Prep W pass 1: per-(n,col) max over d (coalesced reads)
// ---------------------------------------------------------------------------
__global__ __launch_bounds__(256) void prep_w_max(const float* __restrict__ W) {
    __shared__ float sm[8][32];
    const int n  = blockIdx.y;
    const int c0 = blockIdx.x * 32;
    const int c  = threadIdx.x & 31;
    const int dl = threadIdx.x >> 5;
    const float* Wn = W + (size_t)n * PC_DIM * COLS;
    float m = 0.f;
    for (int d = dl; d < PC_DIM; d += 8)
        m = fmaxf(m, fabsf(Wn[(size_t)d * COLS + c0 + c]));
    sm[dl][c] = m;
    __syncthreads();
    if (threadIdx.x < 32) {
        float r = sm[0][threadIdx.x];
#pragma unroll
        for (int i = 1; i < 8; i++) r = fmaxf(r, sm[i][threadIdx.x]);
        g_sW[(size_t)n * COLS + c0 + threadIdx.x] = fmaxf(r, 1e-30f) * (1.f / QSCALE);
    }
}

// ---------------------------------------------------------------------------
// Prep W pass 2: transpose + quantize to int8 digits [n][col][d]
// ---------------------------------------------------------------------------
__global__ __launch_bounds__(256) void prep_w_quant(const float* __restrict__ W) {
    __shared__ float tile[32][33];
    const int n  = blockIdx.z;
    const int c0 = blockIdx.x * 32;
    const int d0 = blockIdx.y * 32;
    const float* Wn = W + (size_t)n * PC_DIM * COLS;
#pragma unroll
    for (int j = 0; j < 4; j++) {
        int d = d0 + threadIdx.y + j * 8;
        tile[threadIdx.y + j * 8][threadIdx.x] = Wn[(size_t)d * COLS + c0 + threadIdx.x];
    }
    __syncthreads();
#pragma unroll
    for (int j = 0; j < 4; j++) {
        int col = c0 + threadIdx.y + j * 8;
        int d = d0 + threadIdx.x;
        float sw = g_sW[(size_t)n * COLS + col];         // broadcast per warp-row
        float x = tile[threadIdx.x][threadIdx.y + j * 8];
        int q = __float2int_rn(x / sw);                  // |q| <= QSCALE
        int b0 = (q + 128) >> 8;
        size_t o = ((size_t)n * COLS + col) * PC_DIM + d;
        g_Wb0[o] = (signed char)b0;
        g_Wb1[o] = (signed char)(q - (b0 << 8));
    }
}

// ---------------------------------------------------------------------------
// Vote GEMM on int8 tensor cores (exact digit arithmetic, 3 MMAs/term-set).
// CTA 128x128, 512 threads, 16 warps (4 wm x 4 wn), warp tile 32x32.
// KCH=64 int8, SW64 smem, 3-stage cp.async.
// ---------------------------------------------------------------------------
#define KCH 64
#define T_A0 0
#define T_A1 8192
#define T_B0 16384
#define T_B1 24576
#define STG_BYTES 32768
#define NSTG 3
#define GEMM_SMEM (NSTG * STG_BYTES)      // 98304
#define NC (PC_DIM / KCH)                 // 8

#define CP_ASYNC(sa, ga) \
    asm volatile("cp.async.cg.shared.global [%0], [%1], 16;" :: "r"(sa), "l"(ga))
#define CP_COMMIT() asm volatile("cp.async.commit_group;" ::: "memory")
#define CP_WAIT(N)  asm volatile("cp.async.wait_group %0;" :: "n"(N))

#define LDSM_X4(r0, r1, r2, r3, a) \
    asm volatile("ldmatrix.sync.aligned.m8n8.x4.shared.b16 {%0,%1,%2,%3}, [%4];" \
        : "=r"(r0), "=r"(r1), "=r"(r2), "=r"(r3) : "r"(a))

#define MMA_S8(d, a, b0, b1) \
    asm volatile("mma.sync.aligned.m16n8k32.row.col.s32.s8.s8.s32 " \
        "{%0,%1,%2,%3}, {%4,%5,%6,%7}, {%8,%9}, {%0,%1,%2,%3};" \
        : "+r"((d)[0]), "+r"((d)[1]), "+r"((d)[2]), "+r"((d)[3]) \
        : "r"((a)[0]), "r"((a)[1]), "r"((a)[2]), "r"((a)[3]), "r"(b0), "r"(b1))

__global__ __launch_bounds__(512, 1) void vote_gemm_i8(void) {
    extern __shared__ char smem[];
    const uint32_t sb = smem_to_u32(smem);
    const int tid  = threadIdx.x;
    const int lane = tid & 31;
    const int warp = tid >> 5;
    const int wm   = warp & 3;          // M block of 32
    const int wn   = warp >> 2;         // N block of 32

    const int n  = blockIdx.z;
    const int bm = blockIdx.y * 128;
    const int bn = blockIdx.x * 128;

    const signed char* A0 = g_Pa0 + (size_t)bm * PP_STRIDE + (size_t)n * PC_DIM;
    const signed char* A1 = g_Pa1 + (size_t)bm * PP_STRIDE + (size_t)n * PC_DIM;
    const signed char* B0 = g_Wb0 + ((size_t)n * COLS + bn) * PC_DIM;
    const signed char* B1 = g_Wb1 + ((size_t)n * COLS + bn) * PC_DIM;

    int S0[2][4][4], S01[2][4][4];
#pragma unroll
    for (int i = 0; i < 2; i++)
#pragma unroll
        for (int j = 0; j < 4; j++)
#pragma unroll
            for (int q = 0; q < 4; q++) { S0[i][j][q] = 0; S01[i][j][q] = 0; }

    const int lrow = lane & 15, lch = lane >> 4;

    // cp.async: 2048 16B-chunks/stage, 4 per thread (p = tensor id)
    auto issue_stage = [&](int c, int buf) {
        const int k0 = c * KCH;
        const uint32_t sbase = sb + buf * STG_BYTES;
        const int row = tid >> 2, ch = tid & 3;
        const uint32_t so = usw64(row * 64 + ch * 16);
        CP_ASYNC(sbase + T_A0 + so, A0 + (size_t)row * PP_STRIDE + k0 + ch * 16);
        CP_ASYNC(sbase + T_A1 + so, A1 + (size_t)row * PP_STRIDE + k0 + ch * 16);
        CP_ASYNC(sbase + T_B0 + so, B0 + (size_t)row * PC_DIM + k0 + ch * 16);
        CP_ASYNC(sbase + T_B1 + so, B1 + (size_t)row * PC_DIM + k0 + ch * 16);
        CP_COMMIT();
    };

    issue_stage(0, 0);
    issue_stage(1, 1);
    issue_stage(2, 2);

    for (int c = 0; c < NC; c++) {
        if (c <= NC - 3)      CP_WAIT(2);
        else if (c == NC - 2) CP_WAIT(1);
        else                  CP_WAIT(0);
        __syncthreads();

        const uint32_t sbase = sb + (c % 3) * STG_BYTES;
#pragma unroll
        for (int ks = 0; ks < 2; ks++) {       // two k32 steps per 64B row
            const uint32_t kb = ks * 32 + lch * 16;
            uint32_t a0f[2][4], a1f[2][4];
#pragma unroll
            for (int mt = 0; mt < 2; mt++) {
                uint32_t ao = usw64((wm * 32 + mt * 16 + lrow) * 64 + kb);
                LDSM_X4(a0f[mt][0], a0f[mt][1], a0f[mt][2], a0f[mt][3], sbase + T_A0 + ao);
                LDSM_X4(a1f[mt][0], a1f[mt][1], a1f[mt][2], a1f[mt][3], sbase + T_A1 + ao);
            }
#pragma unroll
            for (int g = 0; g < 2; g++) {
                uint32_t bo = usw64((wn * 32 + g * 16 + lrow) * 64 + kb);
                uint32_t b0f[4], b1f[4];
                LDSM_X4(b0f[0], b0f[1], b0f[2], b0f[3], sbase + T_B0 + bo);
                LDSM_X4(b1f[0], b1f[1], b1f[2], b1f[3], sbase + T_B1 + bo);
#pragma unroll
                for (int mt = 0; mt < 2; mt++) {
                    MMA_S8(S0[mt][g * 2 + 0],  a0f[mt], b0f[0], b0f[2]);
                    MMA_S8(S0[mt][g * 2 + 1],  a0f[mt], b0f[1], b0f[3]);
                    MMA_S8(S01[mt][g * 2 + 0], a0f[mt], b1f[0], b1f[2]);
                    MMA_S8(S01[mt][g * 2 + 1], a0f[mt], b1f[1], b1f[3]);
                    MMA_S8(S01[mt][g * 2 + 0], a1f[mt], b0f[0], b0f[2]);
                    MMA_S8(S01[mt][g * 2 + 1], a1f[mt], b0f[1], b0f[3]);
                }
            }
        }
        __syncthreads();
        if (c + 3 < NC) issue_stage(c + 3, (c + 3) % 3);
    }

    // epilogue: combine digits, apply scales, fp32 store
#pragma unroll
    for (int mt = 0; mt < 2; mt++) {
        const int r0 = bm + wm * 32 + mt * 16 + (lane >> 2);
        const int r1 = r0 + 8;
        const float sp0 = g_sP[(size_t)r0 * N_ROUTES + n];
        const float sp1 = g_sP[(size_t)r1 * N_ROUTES + n];
#pragma unroll
        for (int j = 0; j < 4; j++) {
            int g = j >> 1, nt = j & 1;
            int col = bn + wn * 32 + g * 16 + nt * 8 + (lane & 3) * 2;
            float sw0 = g_sW[(size_t)n * COLS + col];
            float sw1 = g_sW[(size_t)n * COLS + col + 1];
            float v00 = (65536.f * (float)S0[mt][j][0] + 256.f * (float)S01[mt][j][0]) * sp0 * sw0;
            float v01 = (65536.f * (float)S0[mt][j][1] + 256.f * (float)S01[mt][j][1]) * sp0 * sw1;
            float v10 = (65536.f * (float)S0[mt][j][2] + 256.f * (float)S01[mt][j][2]) * sp1 * sw0;
            float v11 = (65536.f * (float)S0[mt][j][3] + 256.f * (float)S01[mt][j][3]) * sp1 * sw1;
            float* d0 = g_vote + (size_t)r0 * VOTE_PER_B + (size_t)n * COLS + col;
            float* d1 = g_vote + (size_t)r1 * VOTE_PER_B + (size_t)n * COLS + col;
            *(float2*)d0 = make_float2(v00, v01);
            *(float2*)d1 = make_float2(v10, v11);
        }
    }
}

// ---------------------------------------------------------------------------
// Register-resident routing (fp32 votes): 800 threads = 25 warps.
// ---------------------------------------------------------------------------
__device__ __forceinline__ float warp_sum(float v) {
#pragma unroll
    for (int o = 16; o; o >>= 1) v += __shfl_xor_sync(0xffffffffu, v, o);
    return v;
}
__device__ __forceinline__ void warp_sum2(float& a, float& b) {
#pragma unroll
    for (int o = 16; o; o >>= 1) {
        a += __shfl_xor_sync(0xffffffffu, a, o);
        b += __shfl_xor_sync(0xffffffffu, b, o);
    }
}

__global__ __launch_bounds__(800) void routing_kernel(
    const float* __restrict__ prim_act,
    const float* __restrict__ ln_gamma, const float* __restrict__ ln_beta,
    const float* __restrict__ embedding, const float* __restrict__ bias,
    float* __restrict__ out_logits, float* __restrict__ out_act,
    float* __restrict__ out_coef) {
    __shared__ float s_act[N_ROUTES];
    __shared__ float s_agree[N_ROUTES * KCLS];
    __shared__ float s_coef[N_ROUTES * KCLS];

    const int b    = blockIdx.x;
    const int tid  = threadIdx.x;
    const int lane = tid & 31;
    const int m    = tid >> 5;

    float4 v[N_ROUTES];
    {
        const float* base = g_vote + (size_t)b * VOTE_PER_B + m * MC_DIM + lane * 4;
#pragma unroll
        for (int nn = 0; nn < N_ROUTES; nn++)
            v[nn] = *(const float4*)(base + nn * COLS);
    }
    const float4 g4 = ((const float4*)ln_gamma)[lane];
    const float4 b4 = ((const float4*)ln_beta)[lane];
    if (tid < N_ROUTES) s_act[tid] = prim_act[(size_t)b * N_ROUTES + tid];
    __syncthreads();

    float a_r[N_ROUTES];
#pragma unroll
    for (int nn = 0; nn < N_ROUTES; nn++) a_r[nn] = s_act[nn];

    float4 p = make_float4(0.f, 0.f, 0.f, 0.f);
#pragma unroll
    for (int nn = 0; nn < N_ROUTES; nn++) {
        p.x += a_r[nn] * v[nn].x;
        p.y += a_r[nn] * v[nn].y;
        p.z += a_r[nn] * v[nn].z;
        p.w += a_r[nn] * v[nn].w;
    }
    p.x *= (1.f / 25.f); p.y *= (1.f / 25.f); p.z *= (1.f / 25.f); p.w *= (1.f / 25.f);

    auto layernorm = [&](float4& x) {
        float s1 = x.x + x.y + x.z + x.w;
        float s2 = x.x * x.x + x.y * x.y + x.z * x.z + x.w * x.w;
        warp_sum2(s1, s2);
        float mu = s1 * (1.f / MC_DIM);
        float ve = s2 * (1.f / MC_DIM) - mu * mu + 1e-5f;
        float r = rsqrtf(ve);
        r = r * (1.5f - 0.5f * ve * r * r);
        x.x = (x.x - mu) * r * g4.x + b4.x;
        x.y = (x.y - mu) * r * g4.y + b4.y;
        x.z = (x.z - mu) * r * g4.z + b4.z;
        x.w = (x.w - mu) * r * g4.w + b4.w;
    };
    layernorm(p);

    const float scale = 0.08838834764831845f;   // 1/sqrt(128)
#pragma unroll
    for (int it = 1; it <= 2; it++) {
#pragma unroll
        for (int nn = 0; nn < N_ROUTES; nn++) {
            float d = v[nn].x * p.x + v[nn].y * p.y + v[nn].z * p.z + v[nn].w * p.w;
            d = warp_sum(d);
            if (lane == 0) s_agree[nn * KCLS + m] = d * scale;
        }
        __syncthreads();

        if (m < N_ROUTES) {
            float aval = (lane < KCLS) ? s_agree[m * KCLS + lane] : -1e30f;
            float mx = warp_max32(aval);
            float e = (lane < KCLS) ? expf(aval - mx) : 0.f;
            float s = warp_sum(e);
            if (lane < KCLS) s_coef[m * KCLS + lane] = e / s;
        }
        __syncthreads();

        if (it == 2 && tid < N_ROUTES * KCLS)
            out_coef[(size_t)b * (N_ROUTES * KCLS) + tid] = s_coef[tid];

        p = make_float4(0.f, 0.f, 0.f, 0.f);
#pragma unroll
        for (int nn = 0; nn < N_ROUTES; nn++) {
            float ca = s_coef[nn * KCLS + m] * a_r[nn];
            p.x += ca * v[nn].x;
            p.y += ca * v[nn].y;
            p.z += ca * v[nn].z;
            p.w += ca * v[nn].w;
        }
        layernorm(p);
        // no trailing syncthreads needed: next-iteration s_agree writes are
        // WAR-protected by the post-softmax barrier above.
    }

    {
        const float4 e = ((const float4*)(embedding + (size_t)m * MC_DIM))[lane];
        float d = p.x * e.x + p.y * e.y + p.z * e.z + p.w * e.w;
        d = warp_sum(d);
        if (lane == 0) out_logits[(size_t)b * KCLS + m] = d + bias[m];
    }
    if (tid < N_ROUTES) out_act[(size_t)b * N_ROUTES + tid] = a_r[tid];
}

// ---------------------------------------------------------------------------
extern "C" void kernel_launch(void* const* d_in, const int* in_sizes, int n_in,
                              void* d_out, int out_size) {
    const float* prim_pose = (const float*)d_in[0];
    const float* prim_act  = (const float*)d_in[1];
    const float* w         = (const float*)d_in[2];
    const float* ln_gamma  = (const float*)d_in[3];
    const float* ln_beta   = (const float*)d_in[4];
    const float* embedding = (const float*)d_in[5];
    const float* bias      = (const float*)d_in[6];

    float* out        = (float*)d_out;
    float* out_logits = out;
    float* out_act    = out + (size_t)BSZ * KCLS;
    float* out_coef   = out_act + (size_t)BSZ * N_ROUTES;

    prep_p_q<<<(BSZ * N_ROUTES) / 2, 256>>>(prim_pose);
    prep_w_max<<<dim3(COLS / 32, N_ROUTES), 256>>>(w);
    prep_w_quant<<<dim3(COLS / 32, PC_DIM / 32, N_ROUTES), dim3(32, 8)>>>(w);

    cudaFuncSetAttribute(vote_gemm_i8,
                         cudaFuncAttributeMaxDynamicSharedMemorySize, GEMM_SMEM);
    dim3 g(COLS / 128, BSZ / 128, N_ROUTES);   // (25, 32, 7)
    vote_gemm_i8<<<g, 512, GEMM_SMEM>>>();

    routing_kernel<<<BSZ, 800>>>(prim_act, ln_gamma, ln_beta,
                                 embedding, bias,
                                 out_logits, out_act, out_coef);
}

// round 10
// speedup vs baseline: 2.3502x; 2.3502x over previous
#include <cuda_runtime.h>
#include <cuda_bf16.h>
#include <stdint.h>
#include <math.h>

#define N_ROUTES 7
#define PC_DIM   512
#define MC_DIM   128
#define KCLS     25
#define BSZ      4096
#define COLS     (KCLS * MC_DIM)        // 3200
#define VOTE_PER_B (N_ROUTES * COLS)    // 22400
#define PP_STRIDE (N_ROUTES * PC_DIM)   // 3584

__device__ float g_vote[(size_t)BSZ * VOTE_PER_B];                    // 367 MB
__device__ __nv_bfloat16 g_Phi[(size_t)BSZ * PP_STRIDE];
__device__ __nv_bfloat16 g_Plo[(size_t)BSZ * PP_STRIDE];
__device__ __nv_bfloat16 g_Whi[(size_t)N_ROUTES * COLS * PC_DIM];     // [n][col][d]
__device__ __nv_bfloat16 g_Wlo[(size_t)N_ROUTES * COLS * PC_DIM];

__device__ __forceinline__ uint32_t smem_to_u32(const void* p) {
    uint32_t a;
    asm("{ .reg .u64 t; cvta.to.shared.u64 t, %1; cvt.u32.u64 %0, t; }"
        : "=r"(a) : "l"(p));
    return a;
}
__device__ __forceinline__ uint32_t usw64(uint32_t o) {     // SW64 swizzle
    return o ^ ((o >> 3) & 0x30);
}

#define CP_ASYNC(sa, ga) \
    asm volatile("cp.async.cg.shared.global [%0], [%1], 16;" :: "r"(sa), "l"(ga))
#define CP_COMMIT() asm volatile("cp.async.commit_group;" ::: "memory")
#define CP_WAIT(N)  asm volatile("cp.async.wait_group %0;" :: "n"(N))

// ---------------------------------------------------------------------------
// Prep 1: split prim_pose into bf16 hi/lo
// ---------------------------------------------------------------------------
__global__ __launch_bounds__(512) void prep_p_kernel(const float* __restrict__ P) {
    size_t i = (size_t)blockIdx.x * 512 + threadIdx.x;   // float4 index
    float4 x = ((const float4*)P)[i];
    __nv_bfloat16 h0 = __float2bfloat16(x.x);
    __nv_bfloat16 h1 = __float2bfloat16(x.y);
    __nv_bfloat16 h2 = __float2bfloat16(x.z);
    __nv_bfloat16 h3 = __float2bfloat16(x.w);
    __nv_bfloat162* dh = (__nv_bfloat162*)g_Phi;
    __nv_bfloat162* dl = (__nv_bfloat162*)g_Plo;
    dh[2 * i]     = __nv_bfloat162(h0, h1);
    dh[2 * i + 1] = __nv_bfloat162(h2, h3);
    dl[2 * i] = __nv_bfloat162(__float2bfloat16(x.x - __bfloat162float(h0)),
                               __float2bfloat16(x.y - __bfloat162float(h1)));
    dl[2 * i + 1] = __nv_bfloat162(__float2bfloat16(x.z - __bfloat162float(h2)),
                                   __float2bfloat16(x.w - __bfloat162float(h3)));
}

// ---------------------------------------------------------------------------
// Prep 2: transpose+split W[n][d][col] -> Whi/Wlo [n][col][d]
// ---------------------------------------------------------------------------
__global__ __launch_bounds__(256) void prep_w_kernel(const float* __restrict__ W) {
    __shared__ float tile[32][33];
    const int n = blockIdx.z;
    const int c0 = blockIdx.x * 32;
    const int d0 = blockIdx.y * 32;
    const float* Wn = W + (size_t)n * PC_DIM * COLS;
#pragma unroll
    for (int j = 0; j < 4; j++) {
        int d = d0 + threadIdx.y + j * 8;
        tile[threadIdx.y + j * 8][threadIdx.x] = Wn[(size_t)d * COLS + c0 + threadIdx.x];
    }
    __syncthreads();
#pragma unroll
    for (int j = 0; j < 4; j++) {
        int col = c0 + threadIdx.y + j * 8;
        int d = d0 + threadIdx.x;
        float x = tile[threadIdx.x][threadIdx.y + j * 8];
        __nv_bfloat16 h = __float2bfloat16(x);
        size_t o = ((size_t)n * COLS + col) * PC_DIM + d;
        g_Whi[o] = h;
        g_Wlo[o] = __float2bfloat16(x - __bfloat162float(h));
    }
}

// ---------------------------------------------------------------------------
// Vote GEMM (R5, best known): mma.sync bf16 3-term split. CTA 128x128,
// 8 warps (4 wm x 2 wn, warp tile 32x64). KCH=32, SW64 smem, 3-stage cp.async.
// ---------------------------------------------------------------------------
#define KCH 32
#define T_AH 0
#define T_AL 8192
#define T_BH 16384
#define T_BL 24576
#define STG_BYTES 32768
#define NSTG 3
#define GEMM_SMEM (NSTG * STG_BYTES)      // 98304 -> 2 CTAs/SM
#define NC (PC_DIM / KCH)                 // 16

#define LDSM_X4(r0, r1, r2, r3, a) \
    asm volatile("ldmatrix.sync.aligned.m8n8.x4.shared.b16 {%0,%1,%2,%3}, [%4];" \
        : "=r"(r0), "=r"(r1), "=r"(r2), "=r"(r3) : "r"(a))

#define MMA_BF16(d, a, b0, b1) \
    asm volatile("mma.sync.aligned.m16n8k16.row.col.f32.bf16.bf16.f32 " \
        "{%0,%1,%2,%3}, {%4,%5,%6,%7}, {%8,%9}, {%0,%1,%2,%3};" \
        : "+f"((d)[0]), "+f"((d)[1]), "+f"((d)[2]), "+f"((d)[3]) \
        : "r"((a)[0]), "r"((a)[1]), "r"((a)[2]), "r"((a)[3]), "r"(b0), "r"(b1))

__global__ __launch_bounds__(256, 2) void vote_gemm_tc(void) {
    extern __shared__ char smem[];
    const uint32_t sb = smem_to_u32(smem);
    const int tid  = threadIdx.x;
    const int lane = tid & 31;
    const int warp = tid >> 5;
    const int wm   = warp & 3;          // M block of 32
    const int wn   = warp >> 2;         // N block of 64

    const int n  = blockIdx.z;
    const int bm = blockIdx.y * 128;
    const int bn = blockIdx.x * 128;

    const __nv_bfloat16* Ahi = g_Phi + (size_t)bm * PP_STRIDE + (size_t)n * PC_DIM;
    const __nv_bfloat16* Alo = g_Plo + (size_t)bm * PP_STRIDE + (size_t)n * PC_DIM;
    const __nv_bfloat16* Bhi = g_Whi + ((size_t)n * COLS + bn) * PC_DIM;
    const __nv_bfloat16* Blo = g_Wlo + ((size_t)n * COLS + bn) * PC_DIM;

    float acc[2][8][4];
#pragma unroll
    for (int i = 0; i < 2; i++)
#pragma unroll
        for (int j = 0; j < 8; j++)
#pragma unroll
            for (int q = 0; q < 4; q++) acc[i][j][q] = 0.f;

    const int lrow = lane & 15, lch = lane >> 4;

    auto issue_stage = [&](int c, int buf) {
        const int k0 = c * KCH;
        const uint32_t sbase = sb + buf * STG_BYTES;
#pragma unroll
        for (int p = 0; p < 8; p++) {
            int id  = p * 256 + tid;
            int t   = id >> 9;          // 0..3
            int rem = id & 511;
            int row = rem >> 2;
            int ch  = rem & 3;
            uint32_t sa = sbase + t * 8192 + usw64(row * 64 + ch * 16);
            const __nv_bfloat16* g;
            if (t == 0)      g = Ahi + (size_t)row * PP_STRIDE + k0 + ch * 8;
            else if (t == 1) g = Alo + (size_t)row * PP_STRIDE + k0 + ch * 8;
            else if (t == 2) g = Bhi + (size_t)row * PC_DIM + k0 + ch * 8;
            else             g = Blo + (size_t)row * PC_DIM + k0 + ch * 8;
            CP_ASYNC(sa, g);
        }
        CP_COMMIT();
    };

    issue_stage(0, 0);
    issue_stage(1, 1);
    issue_stage(2, 2);

    for (int c = 0; c < NC; c++) {
        if (c <= NC - 3)      CP_WAIT(2);
        else if (c == NC - 2) CP_WAIT(1);
        else                  CP_WAIT(0);
        __syncthreads();

        const uint32_t sbase = sb + (c % 3) * STG_BYTES;
#pragma unroll
        for (int ks = 0; ks < 2; ks++) {
            const uint32_t kb = ks * 32 + lch * 16;
            uint32_t ah[2][4], al[2][4];
#pragma unroll
            for (int mt = 0; mt < 2; mt++) {
                uint32_t ao = usw64((wm * 32 + mt * 16 + lrow) * 64 + kb);
                LDSM_X4(ah[mt][0], ah[mt][1], ah[mt][2], ah[mt][3], sbase + T_AH + ao);
                LDSM_X4(al[mt][0], al[mt][1], al[mt][2], al[mt][3], sbase + T_AL + ao);
            }
#pragma unroll
            for (int g = 0; g < 4; g++) {
                uint32_t bo = usw64((wn * 64 + g * 16 + lrow) * 64 + kb);
                uint32_t bh[4], bl[4];
                LDSM_X4(bh[0], bh[1], bh[2], bh[3], sbase + T_BH + bo);
                LDSM_X4(bl[0], bl[1], bl[2], bl[3], sbase + T_BL + bo);
                MMA_BF16(acc[0][g * 2 + 0], ah[0], bh[0], bh[2]);
                MMA_BF16(acc[0][g * 2 + 1], ah[0], bh[1], bh[3]);
                MMA_BF16(acc[1][g * 2 + 0], ah[1], bh[0], bh[2]);
                MMA_BF16(acc[1][g * 2 + 1], ah[1], bh[1], bh[3]);
                MMA_BF16(acc[0][g * 2 + 0], ah[0], bl[0], bl[2]);
                MMA_BF16(acc[0][g * 2 + 1], ah[0], bl[1], bl[3]);
                MMA_BF16(acc[1][g * 2 + 0], ah[1], bl[0], bl[2]);
                MMA_BF16(acc[1][g * 2 + 1], ah[1], bl[1], bl[3]);
                MMA_BF16(acc[0][g * 2 + 0], al[0], bh[0], bh[2]);
                MMA_BF16(acc[0][g * 2 + 1], al[0], bh[1], bh[3]);
                MMA_BF16(acc[1][g * 2 + 0], al[1], bh[0], bh[2]);
                MMA_BF16(acc[1][g * 2 + 1], al[1], bh[1], bh[3]);
            }
        }
        __syncthreads();
        if (c + 3 < NC) issue_stage(c + 3, (c + 3) % 3);
    }

    // epilogue: direct fp32 stores
#pragma unroll
    for (int mt = 0; mt < 2; mt++) {
#pragma unroll
        for (int j = 0; j < 8; j++) {
            int g = j >> 1, nt = j & 1;
            int row = bm + wm * 32 + mt * 16 + (lane >> 2);
            int col = bn + wn * 64 + g * 16 + nt * 8 + (lane & 3) * 2;
            float* d0 = g_vote + (size_t)row * VOTE_PER_B + (size_t)n * COLS + col;
            float* d1 = d0 + (size_t)8 * VOTE_PER_B;
            *(float2*)d0 = make_float2(acc[mt][j][0], acc[mt][j][1]);
            *(float2*)d1 = make_float2(acc[mt][j][2], acc[mt][j][3]);
        }
    }
}

// ---------------------------------------------------------------------------
// Persistent routing: grid=296 CTAs, 800 threads (25 warps, warp = capsule m).
// Double-buffered cp.async smem prefetch of the next row's 89.6 KB vote slice
// hides DRAM latency; per-row compute runs out of registers.
// ---------------------------------------------------------------------------
#define ROUT_GRID 296
#define ROW_FLOATS VOTE_PER_B                    // 22400
#define ROUT_SMEM (2 * ROW_FLOATS * 4)           // 179200 bytes

__device__ __forceinline__ float warp_sum(float v) {
#pragma unroll
    for (int o = 16; o; o >>= 1) v += __shfl_xor_sync(0xffffffffu, v, o);
    return v;
}
__device__ __forceinline__ float warp_max32(float v) {
#pragma unroll
    for (int o = 16; o; o >>= 1) v = fmaxf(v, __shfl_xor_sync(0xffffffffu, v, o));
    return v;
}
__device__ __forceinline__ void warp_sum2(float& a, float& b) {
#pragma unroll
    for (int o = 16; o; o >>= 1) {
        a += __shfl_xor_sync(0xffffffffu, a, o);
        b += __shfl_xor_sync(0xffffffffu, b, o);
    }
}

__global__ __launch_bounds__(800, 1) void routing_kernel(
    const float* __restrict__ prim_act,
    const float* __restrict__ ln_gamma, const float* __restrict__ ln_beta,
    const float* __restrict__ embedding, const float* __restrict__ bias,
    float* __restrict__ out_logits, float* __restrict__ out_act,
    float* __restrict__ out_coef) {
    extern __shared__ float s_vote[];            // 2 x 22400 floats
    __shared__ float s_agree[N_ROUTES * KCLS];
    __shared__ float s_coef[N_ROUTES * KCLS];

    const int tid  = threadIdx.x;
    const int lane = tid & 31;
    const int m    = tid >> 5;                   // warp id == capsule, 0..24
    const uint32_t sb = smem_to_u32(s_vote);

    // row-invariant loads (hoisted out of the row loop)
    const float4 g4 = ((const float4*)ln_gamma)[lane];
    const float4 b4 = ((const float4*)ln_beta)[lane];
    const float4 em = ((const float4*)(embedding + (size_t)m * MC_DIM))[lane];
    const float  bi = bias[m];

    auto prefetch = [&](int row, int buf) {
        const float4* src = (const float4*)(g_vote + (size_t)row * VOTE_PER_B);
        const uint32_t dst = sb + buf * (ROW_FLOATS * 4);
#pragma unroll
        for (int j = 0; j < 7; j++) {
            int idx = tid + j * 800;             // 5600 float4 total
            CP_ASYNC(dst + idx * 16, src + idx);
        }
        CP_COMMIT();
    };

    prefetch(blockIdx.x, 0);
    int buf = 0;

    for (int r = blockIdx.x; r < BSZ; r += ROUT_GRID) {
        if (r + ROUT_GRID < BSZ) {
            prefetch(r + ROUT_GRID, buf ^ 1);
            CP_WAIT(1);
        } else {
            CP_WAIT(0);
        }
        __syncthreads();

        // per-row activations (same 28B line for all threads -> L1 broadcast)
        float a_r[N_ROUTES];
#pragma unroll
        for (int nn = 0; nn < N_ROUTES; nn++)
            a_r[nn] = prim_act[(size_t)r * N_ROUTES + nn];

        // vote slice: registers from smem
        float4 v[N_ROUTES];
        {
            const float* vb = s_vote + buf * ROW_FLOATS + m * MC_DIM + lane * 4;
#pragma unroll
            for (int nn = 0; nn < N_ROUTES; nn++)
                v[nn] = *(const float4*)(vb + nn * COLS);
        }

        // ---- iteration 0: uniform coefficients ----
        float4 p = make_float4(0.f, 0.f, 0.f, 0.f);
#pragma unroll
        for (int nn = 0; nn < N_ROUTES; nn++) {
            p.x += a_r[nn] * v[nn].x;
            p.y += a_r[nn] * v[nn].y;
            p.z += a_r[nn] * v[nn].z;
            p.w += a_r[nn] * v[nn].w;
        }
        p.x *= (1.f / 25.f); p.y *= (1.f / 25.f);
        p.z *= (1.f / 25.f); p.w *= (1.f / 25.f);

        auto layernorm = [&](float4& x) {
            float s1 = x.x + x.y + x.z + x.w;
            float s2 = x.x * x.x + x.y * x.y + x.z * x.z + x.w * x.w;
            warp_sum2(s1, s2);
            float mu = s1 * (1.f / MC_DIM);
            float ve = s2 * (1.f / MC_DIM) - mu * mu + 1e-5f;
            float rr = rsqrtf(ve);
            rr = rr * (1.5f - 0.5f * ve * rr * rr);
            x.x = (x.x - mu) * rr * g4.x + b4.x;
            x.y = (x.y - mu) * rr * g4.y + b4.y;
            x.z = (x.z - mu) * rr * g4.z + b4.z;
            x.w = (x.w - mu) * rr * g4.w + b4.w;
        };
        layernorm(p);

        const float scale = 0.08838834764831845f;   // 1/sqrt(128)
#pragma unroll
        for (int it = 1; it <= 2; it++) {
#pragma unroll
            for (int nn = 0; nn < N_ROUTES; nn++) {
                float d = v[nn].x * p.x + v[nn].y * p.y + v[nn].z * p.z + v[nn].w * p.w;
                d = warp_sum(d);
                if (lane == 0) s_agree[nn * KCLS + m] = d * scale;
            }
            __syncthreads();

            if (m < N_ROUTES) {
                float aval = (lane < KCLS) ? s_agree[m * KCLS + lane] : -1e30f;
                float mx = warp_max32(aval);
                float e = (lane < KCLS) ? expf(aval - mx) : 0.f;
                float s = warp_sum(e);
                if (lane < KCLS) s_coef[m * KCLS + lane] = e / s;
            }
            __syncthreads();

            if (it == 2 && tid < N_ROUTES * KCLS)
                out_coef[(size_t)r * (N_ROUTES * KCLS) + tid] = s_coef[tid];

            p = make_float4(0.f, 0.f, 0.f, 0.f);
#pragma unroll
            for (int nn = 0; nn < N_ROUTES; nn++) {
                float ca = s_coef[nn * KCLS + m] * a_r[nn];
                p.x += ca * v[nn].x;
                p.y += ca * v[nn].y;
                p.z += ca * v[nn].z;
                p.w += ca * v[nn].w;
            }
            layernorm(p);
            __syncthreads();     // protects s_agree WAR across iterations/rows
        }

        // logits
        {
            float d = p.x * em.x + p.y * em.y + p.z * em.z + p.w * em.w;
            d = warp_sum(d);
            if (lane == 0) out_logits[(size_t)r * KCLS + m] = d + bi;
        }
        if (tid < N_ROUTES)
            out_act[(size_t)r * N_ROUTES + tid] = a_r[tid];

        buf ^= 1;
        __syncthreads();         // all reads of 'buf' done before its re-prefetch
    }
}

// ---------------------------------------------------------------------------
extern "C" void kernel_launch(void* const* d_in, const int* in_sizes, int n_in,
                              void* d_out, int out_size) {
    const float* prim_pose = (const float*)d_in[0];
    const float* prim_act  = (const float*)d_in[1];
    const float* w         = (const float*)d_in[2];
    const float* ln_gamma  = (const float*)d_in[3];
    const float* ln_beta   = (const float*)d_in[4];
    const float* embedding = (const float*)d_in[5];
    const float* bias      = (const float*)d_in[6];

    float* out        = (float*)d_out;
    float* out_logits = out;
    float* out_act    = out + (size_t)BSZ * KCLS;
    float* out_coef   = out_act + (size_t)BSZ * N_ROUTES;

    prep_p_kernel<<<(BSZ * PP_STRIDE) / 4 / 512, 512>>>(prim_pose);
    prep_w_kernel<<<dim3(COLS / 32, PC_DIM / 32, N_ROUTES), dim3(32, 8)>>>(w);

    cudaFuncSetAttribute(vote_gemm_tc,
                         cudaFuncAttributeMaxDynamicSharedMemorySize, GEMM_SMEM);
    dim3 g(COLS / 128, BSZ / 128, N_ROUTES);   // (25, 32, 7)
    vote_gemm_tc<<<g, 256, GEMM_SMEM>>>();

    cudaFuncSetAttribute(routing_kernel,
                         cudaFuncAttributeMaxDynamicSharedMemorySize, ROUT_SMEM);
    routing_kernel<<<ROUT_GRID, 800, ROUT_SMEM>>>(prim_act, ln_gamma, ln_beta,
                                                  embedding, bias,
                                                  out_logits, out_act, out_coef);
}